// round 12
// baseline (speedup 1.0000x reference)
#include <cuda_runtime.h>
#include <math.h>
#include <stdint.h>

// ----------------------------------------------------------------------------
// Problem constants
// ----------------------------------------------------------------------------
#define TT   2048
#define BB   32
#define HH   512
#define NB   64              // CTAs per direction
#define CPB  8               // hidden columns per CTA
#define STR  516             // SMEM row stride in floats
#define NG   4               // independent groups per CTA (8 batch rows each)
#define GB   8               // batch rows per group

// ----------------------------------------------------------------------------
// Device scratch: 8 independent barrier networks (2 dirs x 4 groups)
// ----------------------------------------------------------------------------
__device__ float    g_h[2][2][BB * HH];        // [dir][parity][b*H + j]
__device__ unsigned g_grp[2][NG][8];           // tree leaves (8 groups of 8 CTAs)
__device__ unsigned g_root[2][NG];
__device__ unsigned g_gen[2][NG];              // monotonic generations

struct Args {
    const float* x;
    const float* Wxi[2][3];   // [dir][{Wri,Wci,Wni}]  (I x H, row-major)
    const float* Whh[2][3];   // [dir][{Wrh,Wch,Wnh}]  (H x H, row-major)
    const float* br[2];
    const float* bi[2];
    const float* bni[2];
    const float* bnh[2];
    float*       out;
};

// Packed fp32x2 FMA
__device__ __forceinline__ void ffma2(unsigned long long& d,
                                      unsigned long long a, unsigned long long b)
{
    asm("fma.rn.f32x2 %0, %1, %2, %0;" : "+l"(d) : "l"(a), "l"(b));
}
__device__ __forceinline__ float u64lo(unsigned long long v) {
    return __uint_as_float((unsigned)(v & 0xffffffffull));
}
__device__ __forceinline__ float u64hi(unsigned long long v) {
    return __uint_as_float((unsigned)(v >> 32));
}

// Scoped atomics: no full membar (avoids CCTL.IVALL L1 flush per step)
__device__ __forceinline__ unsigned atom_add_acqrel(unsigned* p, unsigned v)
{
    unsigned old;
    asm volatile("atom.acq_rel.gpu.add.u32 %0, [%1], %2;"
                 : "=r"(old) : "l"(p), "r"(v) : "memory");
    return old;
}
__device__ __forceinline__ unsigned ld_acquire(const unsigned* p)
{
    unsigned v;
    asm volatile("ld.acquire.gpu.u32 %0, [%1];" : "=r"(v) : "l"(p) : "memory");
    return v;
}

// Per-network arrive tree (called by group leader only). acq_rel atomics give
// cumulative release ordering: group's h stores (ordered by bar.sync) are
// visible before gen increments.
__device__ __forceinline__ void net_arrive(int d, int g, int grpIdx)
{
    unsigned a = atom_add_acqrel(&g_grp[d][g][grpIdx], 1u);
    if (((a + 1u) & 7u) == 0u) {
        unsigned r = atom_add_acqrel(&g_root[d][g], 1u);
        if (((r + 1u) & 7u) == 0u)
            atom_add_acqrel(&g_gen[d][g], 1u);
    }
}

// Group-scoped named barrier (64 threads, ids 1..4)
#define GBAR(g) asm volatile("bar.sync %0, 64;" :: "r"((g) + 1) : "memory")

// Fast, overflow-safe activations
__device__ __forceinline__ float fast_sigmoid(float z) {
    return __fdividef(1.0f, 1.0f + __expf(-z));
}
__device__ __forceinline__ float fast_tanh(float z) {
    float a = fabsf(z);
    float e = __expf(-2.0f * a);
    float t = __fdividef(1.0f - e, 1.0f + e);
    return copysignf(t, z);
}

// ----------------------------------------------------------------------------
// Fused persistent kernel, 4 independent batch-groups per CTA.
// Group step: stage x -> bar -> x-GEMM -> wait(own net) -> stage h -> bar ->
//             h-GEMM -> reduce -> activations -> store -> bar -> arrive
// ----------------------------------------------------------------------------
__global__ void __launch_bounds__(256, 1) gru_fused(Args p)
{
    extern __shared__ float smem[];
    float* Wx   = smem;                  // [24][STR]  rows: jl*3 + gate
    float* Wh   = Wx + 24 * STR;         // [24][STR]
    float* xbuf = Wh + 24 * STR;         // [32][STR]  (partitioned per group)
    float* hbuf = xbuf + 32 * STR;       // [32][STR]

    const int tid = threadIdx.x;
    const int dir = blockIdx.x / NB;
    const int blk = blockIdx.x % NB;
    const int grpIdx = blk >> 3;
    const int j0  = blk * CPB;

    const int g    = tid >> 6;           // group 0..3
    const int tidg = tid & 63;
    const int s    = tidg & 15;          // k-split lane
    const int jp   = tidg >> 4;          // j-pair 0..3
    const int b0   = g * GB;             // group's batch base
    const bool leader = (tidg == 0);

    // Load + transpose weight slices with all 256 threads
    for (int idx = tid; idx < 3 * HH * CPB; idx += 256) {
        int gg = idx >> 12;
        int k  = (idx >> 3) & (HH - 1);
        int jl = idx & 7;
        Wx[(jl * 3 + gg) * STR + k] = p.Wxi[dir][gg][(size_t)k * HH + j0 + jl];
        Wh[(jl * 3 + gg) * STR + k] = p.Whh[dir][gg][(size_t)k * HH + j0 + jl];
    }
    __syncthreads();

    // each thread owns one (b, j) output
    const int myb  = b0 + (s & 7);
    const int jcol = j0 + jp * 2 + (s >> 3);
    const float c_br  = p.br [dir][jcol];
    const float c_bi  = p.bi [dir][jcol];
    const float c_bni = p.bni[dir][jcol];
    const float c_bnh = p.bnh[dir][jcol];

    unsigned base = 0;
    if (leader) base = ld_acquire(&g_gen[dir][g]);

    // h0 = 0
    g_h[dir][0][myb * HH + jcol] = 0.0f;
    GBAR(g);
    if (leader) net_arrive(dir, g, grpIdx);

    const float* WxB = &Wx[jp * 6 * STR];
    const float* WhB = &Wh[jp * 6 * STR];
    float* out = p.out;

#define GEMM_ITER(WB, BUF, c0, c1, c2)                                          \
    {                                                                           \
        const int kk = (s << 2) + (i << 6);                                     \
        ulonglong2 w0 = *(const ulonglong2*)&WB[0 * STR + kk];                  \
        ulonglong2 w1 = *(const ulonglong2*)&WB[1 * STR + kk];                  \
        ulonglong2 w2 = *(const ulonglong2*)&WB[2 * STR + kk];                  \
        ulonglong2 w3 = *(const ulonglong2*)&WB[3 * STR + kk];                  \
        ulonglong2 w4 = *(const ulonglong2*)&WB[4 * STR + kk];                  \
        ulonglong2 w5 = *(const ulonglong2*)&WB[5 * STR + kk];                  \
        _Pragma("unroll")                                                       \
        for (int bb = 0; bb < 8; ++bb) {                                        \
            ulonglong2 v = *(const ulonglong2*)&BUF[(b0 + bb) * STR + kk];      \
            ffma2(acc[bb][c0],     v.x, w0.x);  ffma2(acc[bb][c0],     v.y, w0.y); \
            ffma2(acc[bb][c1],     v.x, w1.x);  ffma2(acc[bb][c1],     v.y, w1.y); \
            ffma2(acc[bb][c2],     v.x, w2.x);  ffma2(acc[bb][c2],     v.y, w2.y); \
            ffma2(acc[bb][4 + c0], v.x, w3.x);  ffma2(acc[bb][4 + c0], v.y, w3.y); \
            ffma2(acc[bb][4 + c1], v.x, w4.x);  ffma2(acc[bb][4 + c1], v.y, w4.y); \
            ffma2(acc[bb][4 + c2], v.x, w5.x);  ffma2(acc[bb][4 + c2], v.y, w5.y); \
        }                                                                       \
    }

    for (int st = 0; st < TT; ++st) {
        const int t   = dir ? (TT - 1 - st) : st;
        const int par = st & 1;

        // ---- stage x(t) rows [b0, b0+8) -> xbuf ----
        {
            const float* xrowbase = p.x + ((size_t)t * BB + b0) * HH;
            #pragma unroll
            for (int r = 0; r < 16; ++r) {
                int idx = tidg + r * 64;           // 1024 float4s for the group
                int row = idx >> 7;                // 0..7
                int kk  = (idx & 127) << 2;
                float4 v = __ldg((const float4*)(xrowbase + (size_t)row * HH + kk));
                *(float4*)&xbuf[(b0 + row) * STR + kk] = v;
            }
        }
        GBAR(g);

        // accumulators: [bb][jj*4 + ch], ch: 0=r, 1=c, 2=n_x, 3=n_h
        unsigned long long acc[8][8];
        #pragma unroll
        for (int bb = 0; bb < 8; ++bb)
            #pragma unroll
            for (int q = 0; q < 8; ++q) acc[bb][q] = 0ull;

        // ---- x-GEMM (hides own-network barrier latency) ----
        #pragma unroll
        for (int i = 0; i < 8; ++i) GEMM_ITER(WxB, xbuf, 0, 1, 2)

        // ---- wait for h(t) on this group's network ----
        if (leader) {
            while (ld_acquire(&g_gen[dir][g]) - base < (unsigned)(st + 1)) { }
        }
        GBAR(g);

        // ---- stage h(t) rows [b0, b0+8) -> hbuf (L2-coherent loads) ----
        {
            const float* hrowbase = (const float*)g_h[dir][par] + (size_t)b0 * HH;
            #pragma unroll
            for (int r = 0; r < 16; ++r) {
                int idx = tidg + r * 64;
                int row = idx >> 7;
                int kk  = (idx & 127) << 2;
                float4 v = __ldcv((const float4*)(hrowbase + (size_t)row * HH + kk));
                *(float4*)&hbuf[(b0 + row) * STR + kk] = v;
            }
        }
        GBAR(g);

        // ---- h-GEMM ----
        #pragma unroll
        for (int i = 0; i < 8; ++i) GEMM_ITER(WhB, hbuf, 0, 1, 3)

        // ---- collapse f32x2 pairs ----
        float a64[8][8];
        #pragma unroll
        for (int bb = 0; bb < 8; ++bb)
            #pragma unroll
            for (int q = 0; q < 8; ++q)
                a64[bb][q] = u64lo(acc[bb][q]) + u64hi(acc[bb][q]);

        // ---- targeted exchange reduction over the 16 k-split lanes ----
        const bool hi8 = (s & 8) != 0;
        float r32[8][4];
        #pragma unroll
        for (int bb = 0; bb < 8; ++bb)
            #pragma unroll
            for (int ch = 0; ch < 4; ++ch) {
                float mine = hi8 ? a64[bb][4 + ch] : a64[bb][ch];
                float oth  = hi8 ? a64[bb][ch]     : a64[bb][4 + ch];
                r32[bb][ch] = mine + __shfl_xor_sync(0xffffffffu, oth, 8);
            }
        const bool hi4 = (s & 4) != 0;
        float r16[4][4];
        #pragma unroll
        for (int bl = 0; bl < 4; ++bl)
            #pragma unroll
            for (int ch = 0; ch < 4; ++ch) {
                float mine = hi4 ? r32[bl + 4][ch] : r32[bl][ch];
                float oth  = hi4 ? r32[bl][ch]     : r32[bl + 4][ch];
                r16[bl][ch] = mine + __shfl_xor_sync(0xffffffffu, oth, 4);
            }
        const bool hi2 = (s & 2) != 0;
        float r8[2][4];
        #pragma unroll
        for (int bl = 0; bl < 2; ++bl)
            #pragma unroll
            for (int ch = 0; ch < 4; ++ch) {
                float mine = hi2 ? r16[bl + 2][ch] : r16[bl][ch];
                float oth  = hi2 ? r16[bl][ch]     : r16[bl + 2][ch];
                r8[bl][ch] = mine + __shfl_xor_sync(0xffffffffu, oth, 2);
            }
        const bool hi1 = (s & 1) != 0;
        float r4v[4];
        #pragma unroll
        for (int ch = 0; ch < 4; ++ch) {
            float mine = hi1 ? r8[1][ch] : r8[0][ch];
            float oth  = hi1 ? r8[0][ch] : r8[1][ch];
            r4v[ch] = mine + __shfl_xor_sync(0xffffffffu, oth, 1);
        }

        // ---- activations + state update ----
        const float rg = fast_sigmoid(r4v[0] + c_br);
        const float cg = fast_sigmoid(r4v[1] + c_bi);
        const float ng = fast_tanh(r4v[2] + c_bni + rg * (r4v[3] + c_bnh));
        const float hold = hbuf[myb * STR + jcol];
        const float hnew = ng + cg * (hold - ng);

        g_h[dir][par ^ 1][myb * HH + jcol] = hnew;
        out[((size_t)t * BB + myb) * (2 * HH) + dir * HH + jcol] = hnew;

        GBAR(g);                              // group stores complete
        if (leader) net_arrive(dir, g, grpIdx);
    }
#undef GEMM_ITER
}

// ----------------------------------------------------------------------------
// Launch. Input order: x, Wri_f,Wci_f,Wni_f,Wrh_f,Wch_f,Wnh_f,br_f,bi_f,bni_f,
// bnh_f, Wri_b,Wci_b,Wni_b,Wrh_b,Wch_b,Wnh_b,br_b,bi_b,bni_b,bnh_b
// ----------------------------------------------------------------------------
extern "C" void kernel_launch(void* const* d_in, const int* in_sizes, int n_in,
                              void* d_out, int out_size)
{
    (void)in_sizes; (void)n_in; (void)out_size;

    Args a;
    a.x = (const float*)d_in[0];
    a.Wxi[0][0] = (const float*)d_in[1];
    a.Wxi[0][1] = (const float*)d_in[2];
    a.Wxi[0][2] = (const float*)d_in[3];
    a.Whh[0][0] = (const float*)d_in[4];
    a.Whh[0][1] = (const float*)d_in[5];
    a.Whh[0][2] = (const float*)d_in[6];
    a.br [0] = (const float*)d_in[7];
    a.bi [0] = (const float*)d_in[8];
    a.bni[0] = (const float*)d_in[9];
    a.bnh[0] = (const float*)d_in[10];
    a.Wxi[1][0] = (const float*)d_in[11];
    a.Wxi[1][1] = (const float*)d_in[12];
    a.Wxi[1][2] = (const float*)d_in[13];
    a.Whh[1][0] = (const float*)d_in[14];
    a.Whh[1][1] = (const float*)d_in[15];
    a.Whh[1][2] = (const float*)d_in[16];
    a.br [1] = (const float*)d_in[17];
    a.bi [1] = (const float*)d_in[18];
    a.bni[1] = (const float*)d_in[19];
    a.bnh[1] = (const float*)d_in[20];
    a.out = (float*)d_out;

    const int smem = (48 * STR + 64 * STR) * (int)sizeof(float);   // ~226 KB
    cudaFuncSetAttribute(gru_fused, cudaFuncAttributeMaxDynamicSharedMemorySize, smem);
    gru_fused<<<2 * NB, 256, smem>>>(a);
}

// round 14
// speedup vs baseline: 1.0303x; 1.0303x over previous
#include <cuda_runtime.h>
#include <stdint.h>

#define TT 2048
#define BB 32
#define HH 512
#define NB 64
#define CPB 8

// SMEM byte offsets (dynamic smem)
#define SM_A   1024
#define SM_B   (SM_A + 131072)          // A: 32 rows x 4096B
#define SM_TOT (SM_B + 98304)           // B: 48 rows x 2048B  -> 230400 <= 232448

// ----------------------------------------------------------------------------
// Device scratch: h exchanged as bf16 hi/lo planes
// ----------------------------------------------------------------------------
__device__ __align__(16) unsigned short g_hh[2][2][BB * HH];
__device__ __align__(16) unsigned short g_hl[2][2][BB * HH];
__device__ unsigned g_grp[2][8];
__device__ unsigned g_root[2];
__device__ unsigned g_gen[2];

struct Args {
    const float* x;
    const float* Wxi[2][3];
    const float* Whh[2][3];
    const float* br[2];
    const float* bi[2];
    const float* bni[2];
    const float* bnh[2];
    float*       out;
};

// ----------------------------------------------------------------------------
// Helpers
// ----------------------------------------------------------------------------
__device__ __forceinline__ uint32_t smem_u32(const void* p_) {
    uint32_t a;
    asm("{ .reg .u64 t; cvta.to.shared.u64 t, %1; cvt.u32.u64 %0, t; }" : "=r"(a) : "l"(p_));
    return a;
}
__device__ __forceinline__ unsigned packbf(float lo, float hi) {
    unsigned d;
    asm("cvt.rn.bf16x2.f32 %0, %1, %2;" : "=r"(d) : "f"(hi), "f"(lo));
    return d;
}
__device__ __forceinline__ unsigned short cvtbf(float f) {
    unsigned short h;
    asm("cvt.rn.bf16.f32 %0, %1;" : "=h"(h) : "f"(f));
    return h;
}
__device__ __forceinline__ float lo16f(unsigned u) { return __uint_as_float(u << 16); }
__device__ __forceinline__ float hi16f(unsigned u) { return __uint_as_float(u & 0xffff0000u); }

__device__ __forceinline__ void split8(float4 a, float4 b, uint4& h, uint4& l) {
    h.x = packbf(a.x, a.y);  h.y = packbf(a.z, a.w);
    h.z = packbf(b.x, b.y);  h.w = packbf(b.z, b.w);
    l.x = packbf(a.x - lo16f(h.x), a.y - hi16f(h.x));
    l.y = packbf(a.z - lo16f(h.y), a.w - hi16f(h.y));
    l.z = packbf(b.x - lo16f(h.z), b.y - hi16f(h.z));
    l.w = packbf(b.z - lo16f(h.w), b.w - hi16f(h.w));
}

__device__ __forceinline__ unsigned atom_add_ar(unsigned* p_, unsigned v) {
    unsigned o;
    asm volatile("atom.acq_rel.gpu.add.u32 %0, [%1], %2;" : "=r"(o) : "l"(p_), "r"(v) : "memory");
    return o;
}
__device__ __forceinline__ unsigned ld_acq(const unsigned* p_) {
    unsigned v;
    asm volatile("ld.acquire.gpu.u32 %0, [%1];" : "=r"(v) : "l"(p_) : "memory");
    return v;
}
__device__ __forceinline__ void net_arrive(int d, int g) {
    unsigned a = atom_add_ar(&g_grp[d][g], 1u);
    if (((a + 1u) & 7u) == 0u) {
        unsigned r = atom_add_ar(&g_root[d], 1u);
        if (((r + 1u) & 7u) == 0u) atom_add_ar(&g_gen[d], 1u);
    }
}

__device__ __forceinline__ float fsig(float z) {
    return __fdividef(1.0f, 1.0f + __expf(-z));
}
__device__ __forceinline__ float ftanh(float z) {
    float a = fabsf(z), e = __expf(-2.0f * a);
    return copysignf(__fdividef(1.0f - e, 1.0f + e), z);
}

// ldmatrix x4 (non-transposed, b16)
#define LDX4(R, ADDR)                                                           \
    asm volatile("ldmatrix.sync.aligned.m8n8.x4.shared.b16 {%0,%1,%2,%3}, [%4];" \
        : "=r"((R)[0]), "=r"((R)[1]), "=r"((R)[2]), "=r"((R)[3]) : "r"(ADDR))

// bf16 mma m16n8k16, fp32 accum
#define MMA4(C, A, B0, B1)                                                      \
    asm volatile("mma.sync.aligned.m16n8k16.row.col.f32.bf16.bf16.f32 "         \
        "{%0,%1,%2,%3}, {%4,%5,%6,%7}, {%8,%9}, {%0,%1,%2,%3};"                 \
        : "+f"((C)[0]), "+f"((C)[1]), "+f"((C)[2]), "+f"((C)[3])                \
        : "r"((A)[0]), "r"((A)[1]), "r"((A)[2]), "r"((A)[3]), "r"(B0), "r"(B1))

// ----------------------------------------------------------------------------
// Persistent fused GRU, warp-level tensor cores.
// A rows (K elems, bf16): [x_hi 0..511 | x_lo 512..1023 | h_hi 1024..1535 | h_lo 1536..2047]
//   16B-chunk swizzle within row: phys_chunk = chunk ^ (row & 7)
// B rows n=0..47: n = gemm*24 + gate*8 + jl; row K: [W_hi 0..511 | W_lo 512..1023]
// Warp w: m-half = w&1, gemm = (w>>1)&1, k-half = w>>2; 3 n-tiles (gates)
// ----------------------------------------------------------------------------
__global__ void __launch_bounds__(256, 1) gru_mma(Args p)
{
    extern __shared__ char smem[];
    const uint32_t su = smem_u32(smem);
    const int tid = threadIdx.x, wid = tid >> 5, lane = tid & 31;
    const int dir = blockIdx.x / NB, blk = blockIdx.x % NB, j0 = blk * CPB;

    // ---- weight prep (once): split-bf16, transposed [n][k], swizzled ----
    for (int idx = tid; idx < 48 * 512; idx += 256) {
        int n = idx >> 9, k = idx & 511;
        int g = n / 24, rem = n - g * 24, gate = rem >> 3, jl = rem & 7;
        const float* W = g ? p.Whh[dir][gate] : p.Wxi[dir][gate];
        float v = W[(size_t)k * HH + j0 + jl];
        unsigned short hb = cvtbf(v);
        unsigned short lb = cvtbf(v - __uint_as_float((unsigned)hb << 16));
        char* rowp = smem + SM_B + n * 2048;
        int ib = (k & 7) * 2, x7 = n & 7;
        *(unsigned short*)(rowp + (((k >> 3) ^ x7) << 4) + ib) = hb;
        *(unsigned short*)(rowp + ((((512 + k) >> 3) ^ x7) << 4) + ib) = lb;
    }

    // ---- warp slice setup ----
    const int m0 = (wid & 1) * 16;
    const int g2 = (wid >> 1) & 1;
    const int kh = wid >> 2;
    const int rA = m0 + (lane & 7) + ((lane >> 3) & 1) * 8;
    const uint32_t aXor = (uint32_t)(rA & 7);
    const uint32_t aRow = su + SM_A + (uint32_t)rA * 4096u;
    const uint32_t kcA = (uint32_t)(lane >> 4);
    const uint32_t bXor = (uint32_t)(lane & 7);
    const uint32_t kcB = (uint32_t)(lane >> 3);
    const uint32_t bR0 = su + SM_B + (uint32_t)(g2 * 24 + 0 + (lane & 7)) * 2048u;
    const uint32_t bR1 = su + SM_B + (uint32_t)(g2 * 24 + 8 + (lane & 7)) * 2048u;
    const uint32_t bR2 = su + SM_B + (uint32_t)(g2 * 24 + 16 + (lane & 7)) * 2048u;
    const int aHi = g2 * 1024;

    float* sc = (float*)(smem + SM_A);      // scratch overlay: 2 x 32 x 25 floats

    // ---- warp0 epilogue state ----
    float cbr[8], cbi[8], cbni[8], cbnh[8], hprev[8];
    #pragma unroll
    for (int jl = 0; jl < 8; ++jl) hprev[jl] = 0.0f;
    if (wid == 0) {
        #pragma unroll
        for (int jl = 0; jl < 8; ++jl) {
            cbr[jl]  = __ldg(&p.br [dir][j0 + jl]);
            cbi[jl]  = __ldg(&p.bi [dir][j0 + jl]);
            cbni[jl] = __ldg(&p.bni[dir][j0 + jl]);
            cbnh[jl] = __ldg(&p.bnh[dir][j0 + jl]);
        }
    }

    // ---- h0 = 0 planes + initial arrive ----
    unsigned base = 0;
    if (tid == 0) base = ld_acq(&g_gen[dir]);
    if (tid < BB) {
        uint4 z = make_uint4(0u, 0u, 0u, 0u);
        *(uint4*)&g_hh[dir][0][tid * HH + j0] = z;
        *(uint4*)&g_hl[dir][0][tid * HH + j0] = z;
    }
    __syncthreads();
    if (tid == 0) net_arrive(dir, blk >> 3);

    float* out = p.out;

#define SEGRUN(AOFF, BOFF, D0, D1)                                              \
    _Pragma("unroll")                                                           \
    for (int dd = (D0); dd < (D1); ++dd) {                                      \
        uint32_t ca = (uint32_t)((((AOFF) + dd * 32) >> 3)) + kcA;              \
        uint32_t cb = (uint32_t)((((BOFF) + dd * 32) >> 3)) + kcB;              \
        uint32_t fa0[4], fa1[4], fb0[4], fb1[4], fb2[4];                        \
        LDX4(fa0, aRow + ((ca ^ aXor) << 4));                                   \
        LDX4(fa1, aRow + (((ca + 2) ^ aXor) << 4));                             \
        LDX4(fb0, bR0 + ((cb ^ bXor) << 4));                                    \
        LDX4(fb1, bR1 + ((cb ^ bXor) << 4));                                    \
        LDX4(fb2, bR2 + ((cb ^ bXor) << 4));                                    \
        MMA4(acc0, fa0, fb0[0], fb0[1]);                                        \
        MMA4(acc1, fa0, fb1[0], fb1[1]);                                        \
        MMA4(acc2, fa0, fb2[0], fb2[1]);                                        \
        MMA4(acc0, fa1, fb0[2], fb0[3]);                                        \
        MMA4(acc1, fa1, fb1[2], fb1[3]);                                        \
        MMA4(acc2, fa1, fb2[2], fb2[3]);                                        \
    }

    for (int st = 0; st < TT; ++st) {
        const int t = dir ? (TT - 1 - st) : st;
        const int par = st & 1;

        // 1. stage x(t): fp32 -> split-bf16 -> A x regions (wait shadow)
        {
            const float* xb = p.x + (size_t)t * (BB * HH);
            #pragma unroll
            for (int i = 0; i < 8; ++i) {
                int id = tid + i * 256;
                int row = id >> 6, c8 = id & 63, x7 = row & 7;
                const float4* sp = (const float4*)(xb + row * HH + c8 * 8);
                float4 a = __ldg(sp), b = __ldg(sp + 1);
                uint4 h4, l4;
                split8(a, b, h4, l4);
                char* rowp = smem + SM_A + row * 4096;
                *(uint4*)(rowp + ((c8 ^ x7) << 4)) = h4;
                *(uint4*)(rowp + (((c8 + 64) ^ x7) << 4)) = l4;
            }
        }

        // 2. wait for h(st)
        if (tid == 0) { while (ld_acq(&g_gen[dir]) - base < (unsigned)(st + 1)) { } }
        __syncthreads();

        // 3. stage h planes -> A h regions (raw swizzled copies)
        {
            const unsigned short* hhp = g_hh[dir][par];
            const unsigned short* hlp = g_hl[dir][par];
            #pragma unroll
            for (int i = 0; i < 8; ++i) {
                int id = tid + i * 256;
                int row = id >> 6, c8 = id & 63, x7 = row & 7;
                char* rowp = smem + SM_A + row * 4096;
                uint4 v = __ldcv((const uint4*)(hhp + row * HH + c8 * 8));
                *(uint4*)(rowp + (((c8 + 128) ^ x7) << 4)) = v;
                uint4 v2 = __ldcv((const uint4*)(hlp + row * HH + c8 * 8));
                *(uint4*)(rowp + (((c8 + 192) ^ x7) << 4)) = v2;
            }
        }
        __syncthreads();

        // 4. MMA phase: 3-term split chains over this warp's K-half
        float acc0[4] = {0.f, 0.f, 0.f, 0.f};
        float acc1[4] = {0.f, 0.f, 0.f, 0.f};
        float acc2[4] = {0.f, 0.f, 0.f, 0.f};
        if (kh == 0) { SEGRUN(aHi, 0, 0, 16)  SEGRUN(aHi, 512, 0, 8) }
        else         { SEGRUN(aHi, 512, 8, 16)  SEGRUN(aHi + 512, 0, 0, 16) }
        __syncthreads();

        // 5. K-half combine via scratch (overlay on dead x region)
        {
            const int brow = m0 + (lane >> 2);
            const int cc = (lane & 3) * 2;
            float* sg = sc + g2 * (32 * 25);
            if (kh == 0) {
                #pragma unroll
                for (int gt = 0; gt < 3; ++gt) {
                    float* a4 = (gt == 0) ? acc0 : (gt == 1) ? acc1 : acc2;
                    sg[brow * 25 + gt * 8 + cc]           = a4[0];
                    sg[brow * 25 + gt * 8 + cc + 1]       = a4[1];
                    sg[(brow + 8) * 25 + gt * 8 + cc]     = a4[2];
                    sg[(brow + 8) * 25 + gt * 8 + cc + 1] = a4[3];
                }
            }
            __syncthreads();
            if (kh == 1) {
                #pragma unroll
                for (int gt = 0; gt < 3; ++gt) {
                    float* a4 = (gt == 0) ? acc0 : (gt == 1) ? acc1 : acc2;
                    sg[brow * 25 + gt * 8 + cc]           += a4[0];
                    sg[brow * 25 + gt * 8 + cc + 1]       += a4[1];
                    sg[(brow + 8) * 25 + gt * 8 + cc]     += a4[2];
                    sg[(brow + 8) * 25 + gt * 8 + cc + 1] += a4[3];
                }
            }
            __syncthreads();
        }

        // 6. epilogue (warp 0; lane = batch row)
        if (wid == 0) {
            const float* sx = sc + lane * 25;            // x-part preacts
            const float* sh = sc + 32 * 25 + lane * 25;  // h-part preacts
            float hn[8];
            #pragma unroll
            for (int jl = 0; jl < 8; ++jl) {
                float r = fsig(sx[jl] + sh[jl] + cbr[jl]);
                float c = fsig(sx[8 + jl] + sh[8 + jl] + cbi[jl]);
                float n = ftanh(sx[16 + jl] + cbni[jl] + r * (sh[16 + jl] + cbnh[jl]));
                hn[jl] = n + c * (hprev[jl] - n);
                hprev[jl] = hn[jl];
            }
            float4 q0 = make_float4(hn[0], hn[1], hn[2], hn[3]);
            float4 q1 = make_float4(hn[4], hn[5], hn[6], hn[7]);
            uint4 h4, l4;
            split8(q0, q1, h4, l4);
            *(uint4*)&g_hh[dir][par ^ 1][lane * HH + j0] = h4;
            *(uint4*)&g_hl[dir][par ^ 1][lane * HH + j0] = l4;
            float* op = out + ((size_t)t * BB + lane) * (2 * HH) + dir * HH + j0;
            *(float4*)op = q0;
            *(float4*)(op + 4) = q1;
        }
        __syncthreads();
        if (tid == 0) net_arrive(dir, blk >> 3);
    }
#undef SEGRUN
}

// ----------------------------------------------------------------------------
// Launch. Input order: x, Wri_f,Wci_f,Wni_f,Wrh_f,Wch_f,Wnh_f,br_f,bi_f,bni_f,
// bnh_f, Wri_b,Wci_b,Wni_b,Wrh_b,Wch_b,Wnh_b,br_b,bi_b,bni_b,bnh_b
// ----------------------------------------------------------------------------
extern "C" void kernel_launch(void* const* d_in, const int* in_sizes, int n_in,
                              void* d_out, int out_size)
{
    (void)in_sizes; (void)n_in; (void)out_size;
    Args a;
    a.x = (const float*)d_in[0];
    a.Wxi[0][0] = (const float*)d_in[1];
    a.Wxi[0][1] = (const float*)d_in[2];
    a.Wxi[0][2] = (const float*)d_in[3];
    a.Whh[0][0] = (const float*)d_in[4];
    a.Whh[0][1] = (const float*)d_in[5];
    a.Whh[0][2] = (const float*)d_in[6];
    a.br [0] = (const float*)d_in[7];
    a.bi [0] = (const float*)d_in[8];
    a.bni[0] = (const float*)d_in[9];
    a.bnh[0] = (const float*)d_in[10];
    a.Wxi[1][0] = (const float*)d_in[11];
    a.Wxi[1][1] = (const float*)d_in[12];
    a.Wxi[1][2] = (const float*)d_in[13];
    a.Whh[1][0] = (const float*)d_in[14];
    a.Whh[1][1] = (const float*)d_in[15];
    a.Whh[1][2] = (const float*)d_in[16];
    a.br [1] = (const float*)d_in[17];
    a.bi [1] = (const float*)d_in[18];
    a.bni[1] = (const float*)d_in[19];
    a.bnh[1] = (const float*)d_in[20];
    a.out = (float*)d_out;

    cudaFuncSetAttribute(gru_mma, cudaFuncAttributeMaxDynamicSharedMemorySize, SM_TOT);
    gru_mma<<<2 * NB, 256, SM_TOT>>>(a);
}